// round 1
// baseline (speedup 1.0000x reference)
#include <cuda_runtime.h>

// out[b, s, d] = in[b, s, d] + PE(s, d)
// PE(s, d) = sin(s / 10000^(2d/D)) if d even, cos(...) if d odd
// Shapes: B=8, S=4096, D=1024 (fp32)
//
// Strategy: one thread owns one (s, d-quad). It computes the 4 PE values once
// (exp2f + sinf/cosf) and applies them to all 8 batch images with float4
// vectorized, fully coalesced loads/stores. Traffic is the mandatory
// 1.074 GB; transcendental cost is amortized 8x and hidden under memory.

#define B 8
#define S 4096
#define D 1024
#define DQ (D / 4)        // 256 float4 groups per row
#define SD4 (S * DQ)      // float4 elements per batch image

// -2 * log2(10000) / 1024, computed in double, rounded to float
#define NEG_C 0.02595256324130752f

__global__ __launch_bounds__(256) void pe_add_kernel(
    const float4* __restrict__ in, float4* __restrict__ out)
{
    const int idx = blockIdx.x * 256 + threadIdx.x;   // 0 .. S*DQ-1
    const int s  = idx >> 8;                          // row (0..4095)
    const int dq = idx & 255;                         // float4 column group

    const float sf = (float)s;
    const int d0 = dq * 4;

    // Compute the 4 PE values for this (s, d0..d0+3) once.
    float pe0, pe1, pe2, pe3;
    {
        float w0 = exp2f((float)(d0 + 0) * -NEG_C);
        float w1 = exp2f((float)(d0 + 1) * -NEG_C);
        float w2 = exp2f((float)(d0 + 2) * -NEG_C);
        float w3 = exp2f((float)(d0 + 3) * -NEG_C);
        pe0 = sinf(sf * w0);   // even dim -> sin
        pe1 = cosf(sf * w1);   // odd dim  -> cos
        pe2 = sinf(sf * w2);
        pe3 = cosf(sf * w3);
    }

    // Front-batch the 8 loads for maximum MLP, then add + store.
    float4 v[B];
#pragma unroll
    for (int b = 0; b < B; b++) {
        v[b] = in[b * SD4 + idx];
    }
#pragma unroll
    for (int b = 0; b < B; b++) {
        float4 x = v[b];
        x.x += pe0;
        x.y += pe1;
        x.z += pe2;
        x.w += pe3;
        out[b * SD4 + idx] = x;
    }
}

extern "C" void kernel_launch(void* const* d_in, const int* in_sizes, int n_in,
                              void* d_out, int out_size)
{
    (void)in_sizes; (void)n_in; (void)out_size;
    const float4* in = (const float4*)d_in[0];
    float4* out = (float4*)d_out;

    // S*DQ = 1,048,576 threads -> 4096 blocks of 256
    pe_add_kernel<<<SD4 / 256, 256>>>(in, out);
}

// round 3
// speedup vs baseline: 1.0292x; 1.0292x over previous
#include <cuda_runtime.h>

// out[b, s, d] = in[b, s, d] + PE(s, d)
// B=8, S=4096, D=1024 fp32. Pure HBM-bound streaming add.
//
// R2: revert to per-element exp2f (R0-validated math, rel_err 1.3e-5) —
// the R1 ratio-chain constant was wrong by 6.4e-6 and blew the phase.
// Keep R1's structural changes: front-batched loads (MLP=8), 64-reg
// budget via __launch_bounds__(256,4), streaming ldcs/stcs.

#define B 8
#define S 4096
#define D 1024
#define DQ (D / 4)        // 256 float4 groups per row
#define SD4 (S * DQ)      // float4 elements per batch image

// 2*log2(10000)/1024 (double-rounded)
#define NEG_C 0.02595256324130752f

__global__ __launch_bounds__(256, 4) void pe_add_kernel(
    const float4* __restrict__ in, float4* __restrict__ out)
{
    const int idx = blockIdx.x * 256 + threadIdx.x;   // 0 .. S*DQ-1
    const int s  = idx >> 8;
    const int dq = idx & 255;

    // ---- front-batch all 8 batch loads (MLP = 8) ----
    float4 v0 = __ldcs(in + 0 * SD4 + idx);
    float4 v1 = __ldcs(in + 1 * SD4 + idx);
    float4 v2 = __ldcs(in + 2 * SD4 + idx);
    float4 v3 = __ldcs(in + 3 * SD4 + idx);
    float4 v4 = __ldcs(in + 4 * SD4 + idx);
    float4 v5 = __ldcs(in + 5 * SD4 + idx);
    float4 v6 = __ldcs(in + 6 * SD4 + idx);
    float4 v7 = __ldcs(in + 7 * SD4 + idx);

    // ---- PE for this (s, 4-dim group), computed under the load shadow ----
    const float sf = (float)s;
    const int d0 = dq * 4;

    float w0 = exp2f((float)(d0 + 0) * -NEG_C);
    float w1 = exp2f((float)(d0 + 1) * -NEG_C);
    float w2 = exp2f((float)(d0 + 2) * -NEG_C);
    float w3 = exp2f((float)(d0 + 3) * -NEG_C);

    float pe0 = sinf(sf * w0);   // even dim -> sin
    float pe1 = cosf(sf * w1);   // odd dim  -> cos
    float pe2 = sinf(sf * w2);
    float pe3 = cosf(sf * w3);

    // ---- add + streaming stores ----
#define APPLY(vv, bb)                                            \
    do {                                                         \
        float4 x = vv;                                           \
        x.x += pe0; x.y += pe1; x.z += pe2; x.w += pe3;          \
        __stcs(out + (bb) * SD4 + idx, x);                       \
    } while (0)

    APPLY(v0, 0); APPLY(v1, 1); APPLY(v2, 2); APPLY(v3, 3);
    APPLY(v4, 4); APPLY(v5, 5); APPLY(v6, 6); APPLY(v7, 7);
#undef APPLY
}

extern "C" void kernel_launch(void* const* d_in, const int* in_sizes, int n_in,
                              void* d_out, int out_size)
{
    (void)in_sizes; (void)n_in; (void)out_size;
    const float4* in = (const float4*)d_in[0];
    float4* out = (float4*)d_out;
    pe_add_kernel<<<SD4 / 256, 256>>>(in, out);
}